// round 14
// baseline (speedup 1.0000x reference)
#include <cuda_runtime.h>
#include <math_constants.h>
#include <cstdint>

// SPP: out = concat(x, pool5(x), pool9(x), pool13(x)) along channels.
// Cascade: pool9 = pool5(pool5(x)), pool13 = pool5(pool9(x)), separable.
//
// Base = R10 (best measured: 54.3us bench / 50.4us ncu / DRAM 69%):
// block = 8 contiguous planes, 4 warps; warp = 2 planes, width-16 shuffles,
// pair-max horizontal 5-max, register-ring vertical 5-max, in-place cascade;
// staging STS fused into compute; 32 KB evict-first bulk stores, 2 buffers.
//
// R13 cuts serial overhead:
//  - Section 0 drains PER-WARP (4 x 8 KB bulk ops, __syncwarp only): drain
//    starts when the fastest warp's loads land, not after a block barrier
//    on the slowest.
//  - p=0 pre-compute barrier deleted (buffer 1 fresh).
//  - p=1 buffer-0 recycle is per-warp (each warp overwrites only its own
//    slice, which only its own sec0 bulk op read): per-thread wait_group +
//    __syncwarp, no block barrier.
//  Block-wide barriers: 7 -> 4.
//
// x: (32, 512, 32, 32) f32 -> out: (32, 2048, 32, 32) f32.

#define NCHAN 512
#define HW 1024
#define PLANES (32 * 512)
#define WARPS_PER_BLK 4
#define PLANES_PER_BLK (WARPS_PER_BLK * 2)
#define SEC_FLOATS (PLANES_PER_BLK * HW)          // 8192 floats
#define SEC_BYTES  (SEC_FLOATS * 4)               // 32768 bytes
#define WSEC_BYTES (2 * HW * 4)                   // 8192 bytes (warp slice)
#define SMEM_BYTES (2 * SEC_BYTES)                // 64 KB

__device__ __forceinline__ uint32_t smem_u32(const void* p) {
    uint32_t a;
    asm("{ .reg .u64 t; cvta.to.shared.u64 t, %1; cvt.u32.u64 %0, t; }"
        : "=r"(a) : "l"(p));
    return a;
}

template <int BYTES>
__device__ __forceinline__ void bulk_store_ef(const float* dst, uint32_t s) {
    asm volatile(
        "{\n\t"
        ".reg .b64 pol;\n\t"
        "createpolicy.fractional.L2::evict_first.b64 pol, 1.0;\n\t"
        "cp.async.bulk.global.shared::cta.bulk_group.L2::cache_hint "
        "[%0], [%1], %2, pol;\n\t"
        "}"
        :: "l"(dst), "r"(s), "n"(BYTES) : "memory");
    asm volatile("cp.async.bulk.commit_group;" ::: "memory");
}

__global__ __launch_bounds__(32 * WARPS_PER_BLK)
void spp_kernel(const float* __restrict__ x, float* __restrict__ out) {
    extern __shared__ float sbuf[];               // [2][SEC_FLOATS]

    const int lane = threadIdx.x & 31;
    const int wid  = threadIdx.x >> 5;
    const int sub  = lane >> 4;                   // plane within warp (0/1)
    const int l    = lane & 15;                   // column-pair index

    const int pl_local = wid * 2 + sub;           // 0..7 within block
    const int plane = blockIdx.x * PLANES_PER_BLK + pl_local;   // n*512+c
    const int n  = plane >> 9;
    const int c0 = (blockIdx.x * PLANES_PER_BLK) & (NCHAN - 1);

    const float2* __restrict__ xin =
        (const float2*)(x + (size_t)plane * HW) + l;
    const float* __restrict__ ob =
        out + ((size_t)n * (4 * NCHAN) + c0) * HW;

    // Lane's 2-column strip, all 32 rows, in registers.
    float2 v[32];
    #pragma unroll
    for (int y = 0; y < 32; ++y) v[y] = xin[y * 16];

    float2* stg0 = (float2*)(sbuf)              + pl_local * (HW / 2) + l;
    float2* stg1 = (float2*)(sbuf + SEC_FLOATS) + pl_local * (HW / 2) + l;
    const uint32_t s0 = smem_u32(sbuf);
    const uint32_t s1 = smem_u32(sbuf + SEC_FLOATS);

    // ---- section 0: per-warp staging + per-warp 8 KB bulk store ----
    #pragma unroll
    for (int y = 0; y < 32; ++y) stg0[y * 16] = v[y];
    __syncwarp();
    if (lane == 0) {
        asm volatile("fence.proxy.async.shared::cta;" ::: "memory");
        // warp slice: planes 2*wid, 2*wid+1 of this block's channel run
        bulk_store_ef<WSEC_BYTES>(ob + (size_t)(2 * wid) * HW,
                                  s0 + wid * WSEC_BYTES);
    }

    const unsigned FULL = 0xffffffffu;
    const float NEG = -CUDART_INF_F;

    #pragma unroll
    for (int p = 0; p < 3; ++p) {
        const int b = (p + 1) & 1;                // stage into buf 1,0,1
        float2* stg = b ? stg1 : stg0;

        if (p == 1) {
            // Recycle buf0 per-warp: each warp overwrites only its slice,
            // read only by its own sec0 bulk op. thread0 also has the
            // sec1 group outstanding (keep it in flight).
            if (lane == 0) {
                if (threadIdx.x == 0)
                    asm volatile("cp.async.bulk.wait_group.read 1;" ::: "memory");
                else
                    asm volatile("cp.async.bulk.wait_group.read 0;" ::: "memory");
            }
            __syncwarp();
        }
        if (p == 2) {
            // Recycle buf1 (sec1 was one 32 KB op from thread0): block-wide.
            if (threadIdx.x == 0)
                asm volatile("cp.async.bulk.wait_group.read 1;" ::: "memory");
            __syncthreads();
        }

        // ---- compute pool p; staging stores fused into the loop ----
        float2 r0 = {NEG, NEG}, r1 = {NEG, NEG},
               r2 = {NEG, NEG}, r3 = {NEG, NEG};

        #pragma unroll
        for (int y = 0; y < 34; ++y) {
            float2 h;
            if (y < 32) {
                const float a = v[y].x, bb = v[y].y;
                const float pm = fmaxf(a, bb);
                const float lp = __shfl_up_sync  (FULL, pm, 1, 16);
                const float lb = __shfl_up_sync  (FULL, bb, 1, 16);
                const float ra = __shfl_down_sync(FULL, a,  1, 16);
                const float rp = __shfl_down_sync(FULL, pm, 1, 16);
                h.x = fmaxf(fmaxf(lp, pm), ra);   // cols 2l-2 .. 2l+2
                h.y = fmaxf(fmaxf(lb, pm), rp);   // cols 2l-1 .. 2l+3
            } else {
                h.x = NEG; h.y = NEG;             // bottom padding rows
            }
            if (y >= 2) {
                float2 m;
                m.x = fmaxf(fmaxf(fmaxf(r0.x, r1.x), fmaxf(r2.x, r3.x)), h.x);
                m.y = fmaxf(fmaxf(fmaxf(r0.y, r1.y), fmaxf(r2.y, r3.y)), h.y);
                v[y - 2] = m;                     // in-place: feeds next pool
                stg[(y - 2) * 16] = m;            // fused staging STS
            }
            r0 = r1; r1 = r2; r2 = r3; r3 = h;
        }

        // ---- publish + one 32 KB bulk store for section p+1 ----
        asm volatile("fence.proxy.async.shared::cta;" ::: "memory");
        __syncthreads();
        if (threadIdx.x == 0)
            bulk_store_ef<SEC_BYTES>(ob + (size_t)(p + 1) * NCHAN * HW,
                                     b ? s1 : s0);
    }

    // SMEM must outlive all pending bulk reads (warp-leader groups already
    // retired at p=1; thread0 retires sec2/sec3 here).
    if (threadIdx.x == 0)
        asm volatile("cp.async.bulk.wait_group.read 0;" ::: "memory");
    __syncthreads();
}

extern "C" void kernel_launch(void* const* d_in, const int* in_sizes, int n_in,
                              void* d_out, int out_size) {
    const float* x = (const float*)d_in[0];
    float* out     = (float*)d_out;
    cudaFuncSetAttribute(spp_kernel,
                         cudaFuncAttributeMaxDynamicSharedMemorySize, SMEM_BYTES);
    spp_kernel<<<PLANES / PLANES_PER_BLK, 32 * WARPS_PER_BLK, SMEM_BYTES>>>(x, out);
}